// round 2
// baseline (speedup 1.0000x reference)
#include <cuda_runtime.h>
#include <cuda_bf16.h>
#include <math.h>

// Problem constants (fixed by reference)
#define D_MODEL   2048
#define NUM_HEADS 16
#define QGROUPS   4
#define HEAD_DIM  128
#define M_PER_G   (NUM_HEADS / QGROUPS)   // 4
#define BATCH     2
#define SEQ       2048
#define ROWS      (BATCH * SEQ)           // 4096
#define KV_COLS   (QGROUPS * HEAD_DIM)    // 512

// ---------------- scratch (device globals; no cudaMalloc allowed) ------------
__device__ float g_q[ROWS * D_MODEL];     // 33.5 MB
__device__ float g_k[ROWS * KV_COLS];     //  8.4 MB
__device__ float g_v[ROWS * KV_COLS];     //  8.4 MB
__device__ float g_attn[ROWS * D_MODEL];  // 33.5 MB

// ============================================================================
// Generic GEMM + bias:  C[M,N] = A[M,K] @ B[K,N] + bias[N]
// 64x64 block tile, BK=16, 256 threads, 4x4 per-thread micro-tile.
// As stored transposed ([BK][BM]) so fragments load as LDS.128.
// All dims are multiples of 64/16 in this problem (no bounds checks).
// ============================================================================
#define BM 64
#define BN 64
#define BK 16

__global__ __launch_bounds__(256) void gemm_bias_kernel(
    const float* __restrict__ A, const float* __restrict__ B,
    const float* __restrict__ bias, float* __restrict__ C,
    int M, int N, int K)
{
    __shared__ float As[BK][BM];
    __shared__ float Bs[BK][BN];

    const int tid = threadIdx.x;
    const int tx = tid & 15;        // 0..15
    const int ty = tid >> 4;        // 0..15
    const int brow = blockIdx.y * BM;
    const int bcol = blockIdx.x * BN;

    // global->shared load indices
    const int arow  = tid >> 2;          // 0..63
    const int acol4 = (tid & 3) * 4;     // 0,4,8,12
    const int bkrow = tid >> 4;          // 0..15
    const int bcol4 = (tid & 15) * 4;

    float acc[4][4] = {};

    for (int k0 = 0; k0 < K; k0 += BK) {
        float4 av = *(const float4*)&A[(size_t)(brow + arow) * K + k0 + acol4];
        As[acol4 + 0][arow] = av.x;
        As[acol4 + 1][arow] = av.y;
        As[acol4 + 2][arow] = av.z;
        As[acol4 + 3][arow] = av.w;
        *(float4*)&Bs[bkrow][bcol4] =
            *(const float4*)&B[(size_t)(k0 + bkrow) * N + bcol + bcol4];
        __syncthreads();

        #pragma unroll
        for (int kk = 0; kk < BK; kk++) {
            float4 a = *(const float4*)&As[kk][ty * 4];
            float4 b = *(const float4*)&Bs[kk][tx * 4];
            acc[0][0] += a.x * b.x; acc[0][1] += a.x * b.y; acc[0][2] += a.x * b.z; acc[0][3] += a.x * b.w;
            acc[1][0] += a.y * b.x; acc[1][1] += a.y * b.y; acc[1][2] += a.y * b.z; acc[1][3] += a.y * b.w;
            acc[2][0] += a.z * b.x; acc[2][1] += a.z * b.y; acc[2][2] += a.z * b.z; acc[2][3] += a.z * b.w;
            acc[3][0] += a.w * b.x; acc[3][1] += a.w * b.y; acc[3][2] += a.w * b.z; acc[3][3] += a.w * b.w;
        }
        __syncthreads();
    }

    #pragma unroll
    for (int i = 0; i < 4; i++) {
        const int r = brow + ty * 4 + i;
        #pragma unroll
        for (int j = 0; j < 4; j++) {
            const int c = bcol + tx * 4 + j;
            C[(size_t)r * N + c] = acc[i][j] + bias[c];
        }
    }
}

// ============================================================================
// Flash attention (fp32, online softmax).
// grid = (SEQ/Br, BATCH*NUM_HEADS), block = 256 threads.
// Br=Bc=64, hd=128. Q,K stored transposed in smem for LDS.128 frag loads.
// Each block: Q tile fixed; loop over 32 key tiles.
// O accumulator: thread t owns row (t>>2), dims [(t&3)*32, +32) in registers.
// ============================================================================
#define Br 64
#define Bc 64
#define HD 128
#define ATTN_SMEM ((HD*Br + HD*Bc + Bc*HD + Br*Bc) * (int)sizeof(float)) // 112 KB

__global__ __launch_bounds__(256) void attn_kernel(
    const float* __restrict__ Q,   // [ROWS, D_MODEL]
    const float* __restrict__ K,   // [ROWS, KV_COLS]
    const float* __restrict__ V,   // [ROWS, KV_COLS]
    float* __restrict__ O)         // [ROWS, D_MODEL]
{
    extern __shared__ float sm[];
    float* Qt = sm;                 // [HD][Br]  (Qt[kk][r])
    float* Kt = Qt + HD * Br;       // [HD][Bc]  (Kt[kk][c])
    float* Vs = Kt + HD * Bc;       // [Bc][HD]
    float* S  = Vs + Bc * HD;       // [Br][Bc]

    const int tid = threadIdx.x;
    const int bh = blockIdx.y;                  // b*NUM_HEADS + h
    const int b  = bh / NUM_HEADS;
    const int h  = bh % NUM_HEADS;
    const int g  = h / M_PER_G;
    const int q0 = blockIdx.x * Br;

    const float qscale = 0.08838834764831845f;  // 1/sqrt(128)

    // ---- load Q tile (transposed, pre-scaled) ----
    {
        const int r   = tid >> 2;           // 0..63
        const int kk0 = (tid & 3) * 4;      // 0,4,8,12
        const float* qrow = &Q[(size_t)(b * SEQ + q0 + r) * D_MODEL + h * HD];
        #pragma unroll
        for (int it = 0; it < 8; it++) {
            const int kk = kk0 + it * 16;
            float4 qv = *(const float4*)&qrow[kk];
            Qt[(kk + 0) * Br + r] = qv.x * qscale;
            Qt[(kk + 1) * Br + r] = qv.y * qscale;
            Qt[(kk + 2) * Br + r] = qv.z * qscale;
            Qt[(kk + 3) * Br + r] = qv.w * qscale;
        }
    }

    // per-thread softmax state (replicated x4 per row)
    const int r     = tid >> 2;        // row 0..63
    const int lane4 = tid & 3;
    const int dseg  = lane4 * 32;

    float m_i = -1e30f;
    float l_i = 0.0f;
    float o[32];
    #pragma unroll
    for (int d = 0; d < 32; d++) o[d] = 0.0f;

    const int tx = tid & 15;
    const int ty = tid >> 4;

    for (int s0 = 0; s0 < SEQ; s0 += Bc) {
        __syncthreads();  // prior PV done with Vs/S; Qt ready on first iter

        // ---- load K tile (transposed) and V tile (natural) ----
        {
            const int j   = tid >> 2;
            const int c0  = (tid & 3) * 4;
            const float* krow = &K[(size_t)(b * SEQ + s0 + j) * KV_COLS + g * HD];
            const float* vrow = &V[(size_t)(b * SEQ + s0 + j) * KV_COLS + g * HD];
            #pragma unroll
            for (int it = 0; it < 8; it++) {
                const int kk = c0 + it * 16;
                float4 kv = *(const float4*)&krow[kk];
                Kt[(kk + 0) * Bc + j] = kv.x;
                Kt[(kk + 1) * Bc + j] = kv.y;
                Kt[(kk + 2) * Bc + j] = kv.z;
                Kt[(kk + 3) * Bc + j] = kv.w;
                *(float4*)&Vs[j * HD + kk] = *(const float4*)&vrow[kk];
            }
        }
        __syncthreads();

        // ---- S = (Q*scale) @ K^T : thread (ty,tx) -> S[4ty..][4tx..] ----
        {
            float acc[4][4] = {};
            #pragma unroll 8
            for (int kk = 0; kk < HD; kk++) {
                float4 a = *(const float4*)&Qt[kk * Br + ty * 4];
                float4 bb = *(const float4*)&Kt[kk * Bc + tx * 4];
                acc[0][0] += a.x * bb.x; acc[0][1] += a.x * bb.y; acc[0][2] += a.x * bb.z; acc[0][3] += a.x * bb.w;
                acc[1][0] += a.y * bb.x; acc[1][1] += a.y * bb.y; acc[1][2] += a.y * bb.z; acc[1][3] += a.y * bb.w;
                acc[2][0] += a.z * bb.x; acc[2][1] += a.z * bb.y; acc[2][2] += a.z * bb.z; acc[2][3] += a.z * bb.w;
                acc[3][0] += a.w * bb.x; acc[3][1] += a.w * bb.y; acc[3][2] += a.w * bb.z; acc[3][3] += a.w * bb.w;
            }
            #pragma unroll
            for (int i = 0; i < 4; i++)
                #pragma unroll
                for (int j = 0; j < 4; j++)
                    S[(ty * 4 + i) * Bc + tx * 4 + j] = acc[i][j];
        }
        __syncthreads();

        // ---- online softmax (4 lanes per row) + PV accumulate ----
        {
            const int jbase = lane4 * 16;
            float tmax = -1e30f;
            #pragma unroll
            for (int jj = 0; jj < 16; jj++)
                tmax = fmaxf(tmax, S[r * Bc + jbase + jj]);
            tmax = fmaxf(tmax, __shfl_xor_sync(0xffffffffu, tmax, 1));
            tmax = fmaxf(tmax, __shfl_xor_sync(0xffffffffu, tmax, 2));

            const float mnew = fmaxf(m_i, tmax);
            const float corr = __expf(m_i - mnew);

            float psum = 0.0f;
            #pragma unroll
            for (int jj = 0; jj < 16; jj++) {
                const int idx = r * Bc + jbase + jj;
                float p = __expf(S[idx] - mnew);
                S[idx] = p;
                psum += p;
            }
            psum += __shfl_xor_sync(0xffffffffu, psum, 1);
            psum += __shfl_xor_sync(0xffffffffu, psum, 2);

            l_i = l_i * corr + psum;
            m_i = mnew;
            #pragma unroll
            for (int d = 0; d < 32; d++) o[d] *= corr;

            __syncwarp();  // all 4 lanes' P writes visible within the warp

            #pragma unroll 4
            for (int j = 0; j < Bc; j++) {
                const float p = S[r * Bc + j];
                const float* vrow = &Vs[j * HD + dseg];
                #pragma unroll
                for (int d4 = 0; d4 < 32; d4 += 4) {
                    float4 vv = *(const float4*)&vrow[d4];
                    o[d4 + 0] += p * vv.x;
                    o[d4 + 1] += p * vv.y;
                    o[d4 + 2] += p * vv.z;
                    o[d4 + 3] += p * vv.w;
                }
            }
        }
    }

    // ---- finalize: O = o / l ----
    {
        const float inv_l = 1.0f / l_i;
        float* orow = &O[(size_t)(b * SEQ + q0 + r) * D_MODEL + h * HD + dseg];
        #pragma unroll
        for (int d4 = 0; d4 < 32; d4 += 4) {
            float4 ov;
            ov.x = o[d4 + 0] * inv_l;
            ov.y = o[d4 + 1] * inv_l;
            ov.z = o[d4 + 2] * inv_l;
            ov.w = o[d4 + 3] * inv_l;
            *(float4*)&orow[d4] = ov;
        }
    }
}

// ============================================================================
// Launch
// ============================================================================
extern "C" void kernel_launch(void* const* d_in, const int* in_sizes, int n_in,
                              void* d_out, int out_size)
{
    const float* x  = (const float*)d_in[0];
    const float* Wq = (const float*)d_in[1];
    const float* bq = (const float*)d_in[2];
    const float* Wk = (const float*)d_in[3];
    const float* bk = (const float*)d_in[4];
    const float* Wv = (const float*)d_in[5];
    const float* bv = (const float*)d_in[6];
    const float* Wo = (const float*)d_in[7];
    const float* bo = (const float*)d_in[8];
    float* out = (float*)d_out;

    float *q, *k, *v, *attn;
    cudaGetSymbolAddress((void**)&q,    g_q);
    cudaGetSymbolAddress((void**)&k,    g_k);
    cudaGetSymbolAddress((void**)&v,    g_v);
    cudaGetSymbolAddress((void**)&attn, g_attn);

    // QKV projections
    gemm_bias_kernel<<<dim3(D_MODEL / BN, ROWS / BM), 256>>>(
        x, Wq, bq, q, ROWS, D_MODEL, D_MODEL);
    gemm_bias_kernel<<<dim3(KV_COLS / BN, ROWS / BM), 256>>>(
        x, Wk, bk, k, ROWS, KV_COLS, D_MODEL);
    gemm_bias_kernel<<<dim3(KV_COLS / BN, ROWS / BM), 256>>>(
        x, Wv, bv, v, ROWS, KV_COLS, D_MODEL);

    // Attention
    static bool attr_set = false;
    cudaFuncSetAttribute(attn_kernel,
                         cudaFuncAttributeMaxDynamicSharedMemorySize, ATTN_SMEM);
    (void)attr_set;
    attn_kernel<<<dim3(SEQ / Br, BATCH * NUM_HEADS), 256, ATTN_SMEM>>>(q, k, v, attn);

    // Output projection
    gemm_bias_kernel<<<dim3(D_MODEL / BN, ROWS / BM), 256>>>(
        attn, Wo, bo, out, ROWS, D_MODEL, D_MODEL);
}

// round 3
// speedup vs baseline: 6.4392x; 6.4392x over previous
#include <cuda_runtime.h>
#include <cstdint>
#include <cstddef>

#define D_MODEL   2048
#define NUM_HEADS 16
#define QGROUPS   4
#define HEAD_DIM  128
#define BATCH     2
#define SEQ       2048
#define ROWS      (BATCH * SEQ)
#define KV_COLS   (QGROUPS * HEAD_DIM)

// ---------------- scratch ----------------
__device__ float g_x[ROWS * D_MODEL];
__device__ float g_wq[D_MODEL * D_MODEL];
__device__ float g_wk[D_MODEL * KV_COLS];
__device__ float g_wv[D_MODEL * KV_COLS];
__device__ float g_wo[D_MODEL * D_MODEL];
__device__ float g_q[ROWS * D_MODEL];
__device__ float g_k[ROWS * KV_COLS];
__device__ float g_v[ROWS * KV_COLS];
__device__ float g_attn[ROWS * D_MODEL];

// ---------------- helpers ----------------
__device__ __forceinline__ float rnaf(float x) {
    uint32_t u;
    asm("cvt.rna.tf32.f32 %0, %1;" : "=r"(u) : "f"(x));
    return __uint_as_float(u);
}
__device__ __forceinline__ void mma8(float* d, const float* a, const float* b) {
    asm volatile(
        "mma.sync.aligned.m16n8k8.row.col.f32.tf32.tf32.f32 "
        "{%0,%1,%2,%3}, {%4,%5,%6,%7}, {%8,%9}, {%0,%1,%2,%3};\n"
        : "+f"(d[0]), "+f"(d[1]), "+f"(d[2]), "+f"(d[3])
        : "r"(__float_as_uint(a[0])), "r"(__float_as_uint(a[1])),
          "r"(__float_as_uint(a[2])), "r"(__float_as_uint(a[3])),
          "r"(__float_as_uint(b[0])), "r"(__float_as_uint(b[1])));
}
__device__ __forceinline__ void cp16(void* smem, const void* gmem) {
    uint32_t s = (uint32_t)__cvta_generic_to_shared(smem);
    asm volatile("cp.async.cg.shared.global [%0], [%1], 16;\n" :: "r"(s), "l"(gmem));
}
__device__ __forceinline__ void cp_commit() { asm volatile("cp.async.commit_group;\n"); }
template<int N> __device__ __forceinline__ void cp_wait() {
    asm volatile("cp.async.wait_group %0;\n" :: "n"(N));
}

__global__ void round_tf32_kernel(const float* __restrict__ in, float* __restrict__ out, int n) {
    int i = blockIdx.x * blockDim.x + threadIdx.x;
    if (i < n) out[i] = rnaf(in[i]);
}

// ============================================================================
// GEMM tf32: C[M,N] = A[M,K]@B[K,N] + bias. CTA 128x128, BK=32, 128 thr,
// 4 warps (2x2), warp tile 64x64. 2-stage cp.async.
// ============================================================================
#define GAS (128 * 36)
#define GBS (32 * 136)
#define GEMM_SMEM ((2 * GAS + 2 * GBS) * (int)sizeof(float))

__global__ __launch_bounds__(128) void gemm_tf32(
    const float* __restrict__ A, const float* __restrict__ B,
    const float* __restrict__ bias, float* __restrict__ C,
    int M, int N, int K, int round_out)
{
    extern __shared__ float sm[];
    float* As = sm;
    float* Bs = sm + 2 * GAS;

    const int tid = threadIdx.x, lane = tid & 31, wid = tid >> 5;
    const int gr = lane >> 2, tig = lane & 3;
    const int wm = wid >> 1, wn = wid & 1;
    const int brow = blockIdx.y * 128, bcol = blockIdx.x * 128;

    const int ar = tid >> 3, ac = (tid & 7) * 4;
    const int brw = tid >> 5, bcl = (tid & 31) * 4;

    float acc[4][8][4];
    #pragma unroll
    for (int i = 0; i < 4; i++)
        #pragma unroll
        for (int j = 0; j < 8; j++)
            #pragma unroll
            for (int q = 0; q < 4; q++) acc[i][j][q] = 0.f;

    const int NIT = K >> 5;

    #pragma unroll
    for (int j = 0; j < 8; j++)
        cp16(&As[(ar + 16 * j) * 36 + ac], &A[(size_t)(brow + ar + 16 * j) * K + ac]);
    #pragma unroll
    for (int j = 0; j < 8; j++)
        cp16(&Bs[(brw + 4 * j) * 136 + bcl], &B[(size_t)(brw + 4 * j) * N + bcol + bcl]);
    cp_commit();

    for (int it = 0; it < NIT; it++) {
        if (it + 1 < NIT) {
            const int st = (it + 1) & 1, k0 = (it + 1) * 32;
            #pragma unroll
            for (int j = 0; j < 8; j++)
                cp16(&As[st * GAS + (ar + 16 * j) * 36 + ac],
                     &A[(size_t)(brow + ar + 16 * j) * K + k0 + ac]);
            #pragma unroll
            for (int j = 0; j < 8; j++)
                cp16(&Bs[st * GBS + (brw + 4 * j) * 136 + bcl],
                     &B[(size_t)(k0 + brw + 4 * j) * N + bcol + bcl]);
            cp_commit();
            cp_wait<1>();
        } else {
            cp_wait<0>();
        }
        __syncthreads();

        const float* as = &As[(it & 1) * GAS];
        const float* bs = &Bs[(it & 1) * GBS];
        #pragma unroll
        for (int ks = 0; ks < 4; ks++) {
            const int kk = ks * 8 + tig;
            float af[4][4], bf[8][2];
            #pragma unroll
            for (int mt = 0; mt < 4; mt++) {
                const int r = wm * 64 + mt * 16 + gr;
                af[mt][0] = as[r * 36 + kk];
                af[mt][1] = as[(r + 8) * 36 + kk];
                af[mt][2] = as[r * 36 + kk + 4];
                af[mt][3] = as[(r + 8) * 36 + kk + 4];
            }
            #pragma unroll
            for (int nt = 0; nt < 8; nt++) {
                const int n = wn * 64 + nt * 8 + gr;
                bf[nt][0] = bs[kk * 136 + n];
                bf[nt][1] = bs[(kk + 4) * 136 + n];
            }
            #pragma unroll
            for (int mt = 0; mt < 4; mt++)
                #pragma unroll
                for (int nt = 0; nt < 8; nt++)
                    mma8(acc[mt][nt], af[mt], bf[nt]);
        }
        __syncthreads();
    }

    #pragma unroll
    for (int mt = 0; mt < 4; mt++) {
        const int r0 = brow + wm * 64 + mt * 16 + gr;
        #pragma unroll
        for (int nt = 0; nt < 8; nt++) {
            const int c = bcol + wn * 64 + nt * 8 + 2 * tig;
            const float b0 = bias[c], b1 = bias[c + 1];
            float v0 = acc[mt][nt][0] + b0, v1 = acc[mt][nt][1] + b1;
            float v2 = acc[mt][nt][2] + b0, v3 = acc[mt][nt][3] + b1;
            if (round_out) { v0 = rnaf(v0); v1 = rnaf(v1); v2 = rnaf(v2); v3 = rnaf(v3); }
            float2 p0; p0.x = v0; p0.y = v1;
            float2 p1; p1.x = v2; p1.y = v3;
            *(float2*)&C[(size_t)r0 * N + c] = p0;
            *(float2*)&C[(size_t)(r0 + 8) * N + c] = p1;
        }
    }
}

// ============================================================================
// Flash attention tf32 mma. Br=Bc=64, HD=128, 8 warps (wm 0..1 x wn 0..3).
// S warp tile 32x16; PV warp tile 32x32. grid=(SEQ/64, BATCH*NUM_HEADS).
// ============================================================================
#define QS_OFF 0
#define KS_OFF 8448                 // 64*132
#define VS_OFF (KS_OFF + 8448)      // 64*132
#define SS_OFF (VS_OFF + 8704)      // 64*136
#define MS_OFF (SS_OFF + 4352)      // 64*68
#define LS_OFF (MS_OFF + 64)
#define CR_OFF (LS_OFF + 64)
#define ATT_SMEM ((CR_OFF + 64) * (int)sizeof(float))   // 120,576 B

__global__ __launch_bounds__(256) void attn_tf32(
    const float* __restrict__ Q, const float* __restrict__ Kg,
    const float* __restrict__ Vg, float* __restrict__ O)
{
    extern __shared__ float sm[];
    float* Qs = sm + QS_OFF;      // [64][132]
    float* Ks = sm + KS_OFF;      // [64][132]
    float* Vs = sm + VS_OFF;      // [64][136]
    float* Ss = sm + SS_OFF;      // [64][68]
    float* m_s = sm + MS_OFF;
    float* l_s = sm + LS_OFF;
    float* cr_s = sm + CR_OFF;

    const int tid = threadIdx.x, lane = tid & 31, wid = tid >> 5;
    const int gr = lane >> 2, tig = lane & 3;
    const int wm = wid >> 2, wn = wid & 3;

    const int bh = blockIdx.y;
    const int b = bh >> 4, h = bh & 15, g = h >> 2;
    const int q0 = blockIdx.x * 64;
    const float qscale = 0.08838834764831845f;

    // Q tile: scale + round
    {
        const int r = tid >> 2, c0 = (tid & 3) * 32;
        const float* qrow = &Q[(size_t)(b * SEQ + q0 + r) * D_MODEL + h * HEAD_DIM + c0];
        float* qs = &Qs[r * 132 + c0];
        #pragma unroll
        for (int i = 0; i < 8; i++) {
            float4 v = *(const float4*)&qrow[4 * i];
            v.x = rnaf(v.x * qscale); v.y = rnaf(v.y * qscale);
            v.z = rnaf(v.z * qscale); v.w = rnaf(v.w * qscale);
            *(float4*)&qs[4 * i] = v;
        }
    }
    if (tid < 64) { m_s[tid] = -1e30f; l_s[tid] = 0.f; }

    float oacc[2][4][4];
    #pragma unroll
    for (int i = 0; i < 2; i++)
        #pragma unroll
        for (int j = 0; j < 4; j++)
            #pragma unroll
            for (int q = 0; q < 4; q++) oacc[i][j][q] = 0.f;

    const int krow = tid >> 2, kc = (tid & 3) * 32;
    const int srow = tid >> 2, scol0 = (tid & 3) * 16;

    for (int s0 = 0; s0 < SEQ; s0 += 64) {
        __syncthreads();
        // K,V tiles via cp.async
        {
            const float* kp = &Kg[(size_t)(b * SEQ + s0 + krow) * KV_COLS + g * HEAD_DIM + kc];
            const float* vp = &Vg[(size_t)(b * SEQ + s0 + krow) * KV_COLS + g * HEAD_DIM + kc];
            float* ks = &Ks[krow * 132 + kc];
            float* vs = &Vs[krow * 136 + kc];
            #pragma unroll
            for (int i = 0; i < 8; i++) cp16(ks + 4 * i, kp + 4 * i);
            #pragma unroll
            for (int i = 0; i < 8; i++) cp16(vs + 4 * i, vp + 4 * i);
            cp_commit(); cp_wait<0>();
        }
        __syncthreads();

        // S = Q @ K^T : warp tile 32x16
        float sacc[2][2][4];
        #pragma unroll
        for (int i = 0; i < 2; i++)
            #pragma unroll
            for (int j = 0; j < 2; j++)
                #pragma unroll
                for (int q = 0; q < 4; q++) sacc[i][j][q] = 0.f;
        #pragma unroll
        for (int ks = 0; ks < 16; ks++) {
            const int kk = ks * 8 + tig;
            float af[2][4], bf[2][2];
            #pragma unroll
            for (int mt = 0; mt < 2; mt++) {
                const int r = wm * 32 + mt * 16 + gr;
                af[mt][0] = Qs[r * 132 + kk];
                af[mt][1] = Qs[(r + 8) * 132 + kk];
                af[mt][2] = Qs[r * 132 + kk + 4];
                af[mt][3] = Qs[(r + 8) * 132 + kk + 4];
            }
            #pragma unroll
            for (int nt = 0; nt < 2; nt++) {
                const int n = wn * 16 + nt * 8 + gr;
                bf[nt][0] = Ks[n * 132 + kk];
                bf[nt][1] = Ks[n * 132 + kk + 4];
            }
            #pragma unroll
            for (int mt = 0; mt < 2; mt++)
                #pragma unroll
                for (int nt = 0; nt < 2; nt++)
                    mma8(sacc[mt][nt], af[mt], bf[nt]);
        }
        // write S to smem
        #pragma unroll
        for (int mt = 0; mt < 2; mt++) {
            const int r = wm * 32 + mt * 16 + gr;
            #pragma unroll
            for (int nt = 0; nt < 2; nt++) {
                const int c = wn * 16 + nt * 8 + 2 * tig;
                Ss[r * 68 + c] = sacc[mt][nt][0];
                Ss[r * 68 + c + 1] = sacc[mt][nt][1];
                Ss[(r + 8) * 68 + c] = sacc[mt][nt][2];
                Ss[(r + 8) * 68 + c + 1] = sacc[mt][nt][3];
            }
        }
        __syncthreads();

        // online softmax: 4 lanes per row, 16 cols each
        {
            float* srw = &Ss[srow * 68 + scol0];
            float tmax = -1e30f;
            #pragma unroll
            for (int j = 0; j < 16; j++) tmax = fmaxf(tmax, srw[j]);
            tmax = fmaxf(tmax, __shfl_xor_sync(0xffffffffu, tmax, 1));
            tmax = fmaxf(tmax, __shfl_xor_sync(0xffffffffu, tmax, 2));
            const float mold = m_s[srow];
            const float mnew = fmaxf(mold, tmax);
            const float corr = __expf(mold - mnew);
            float psum = 0.f;
            #pragma unroll
            for (int j = 0; j < 16; j++) {
                float p = __expf(srw[j] - mnew);
                srw[j] = rnaf(p);
                psum += p;
            }
            psum += __shfl_xor_sync(0xffffffffu, psum, 1);
            psum += __shfl_xor_sync(0xffffffffu, psum, 2);
            if ((tid & 3) == 0) {
                m_s[srow] = mnew;
                cr_s[srow] = corr;
                l_s[srow] = l_s[srow] * corr + psum;
            }
        }
        __syncthreads();

        // O = O*corr + P @ V : warp tile 32x32
        #pragma unroll
        for (int mt = 0; mt < 2; mt++) {
            const float c0 = cr_s[wm * 32 + mt * 16 + gr];
            const float c1 = cr_s[wm * 32 + mt * 16 + gr + 8];
            #pragma unroll
            for (int nt = 0; nt < 4; nt++) {
                oacc[mt][nt][0] *= c0; oacc[mt][nt][1] *= c0;
                oacc[mt][nt][2] *= c1; oacc[mt][nt][3] *= c1;
            }
        }
        #pragma unroll
        for (int ksv = 0; ksv < 8; ksv++) {
            const int kk = ksv * 8 + tig;
            float af[2][4], bf[4][2];
            #pragma unroll
            for (int mt = 0; mt < 2; mt++) {
                const int r = wm * 32 + mt * 16 + gr;
                af[mt][0] = Ss[r * 68 + kk];
                af[mt][1] = Ss[(r + 8) * 68 + kk];
                af[mt][2] = Ss[r * 68 + kk + 4];
                af[mt][3] = Ss[(r + 8) * 68 + kk + 4];
            }
            #pragma unroll
            for (int nt = 0; nt < 4; nt++) {
                const int n = wn * 32 + nt * 8 + gr;
                bf[nt][0] = Vs[kk * 136 + n];
                bf[nt][1] = Vs[(kk + 4) * 136 + n];
            }
            #pragma unroll
            for (int mt = 0; mt < 2; mt++)
                #pragma unroll
                for (int nt = 0; nt < 4; nt++)
                    mma8(oacc[mt][nt], af[mt], bf[nt]);
        }
    }

    // finalize
    #pragma unroll
    for (int mt = 0; mt < 2; mt++) {
        const int r = wm * 32 + mt * 16 + gr;
        const float il0 = 1.f / l_s[r], il1 = 1.f / l_s[r + 8];
        float* o0 = &O[(size_t)(b * SEQ + q0 + r) * D_MODEL + h * HEAD_DIM];
        float* o1 = &O[(size_t)(b * SEQ + q0 + r + 8) * D_MODEL + h * HEAD_DIM];
        #pragma unroll
        for (int nt = 0; nt < 4; nt++) {
            const int c = wn * 32 + nt * 8 + 2 * tig;
            float2 p0, p1;
            p0.x = rnaf(oacc[mt][nt][0] * il0); p0.y = rnaf(oacc[mt][nt][1] * il0);
            p1.x = rnaf(oacc[mt][nt][2] * il1); p1.y = rnaf(oacc[mt][nt][3] * il1);
            *(float2*)&o0[c] = p0;
            *(float2*)&o1[c] = p1;
        }
    }
}

// ============================================================================
extern "C" void kernel_launch(void* const* d_in, const int* in_sizes, int n_in,
                              void* d_out, int out_size)
{
    const float* x  = (const float*)d_in[0];
    const float* Wq = (const float*)d_in[1];
    const float* bq = (const float*)d_in[2];
    const float* Wk = (const float*)d_in[3];
    const float* bk = (const float*)d_in[4];
    const float* Wv = (const float*)d_in[5];
    const float* bv = (const float*)d_in[6];
    const float* Wo = (const float*)d_in[7];
    const float* bo = (const float*)d_in[8];
    float* out = (float*)d_out;

    float *xr, *wq, *wk, *wv, *wo, *q, *k, *v, *attn;
    cudaGetSymbolAddress((void**)&xr, g_x);
    cudaGetSymbolAddress((void**)&wq, g_wq);
    cudaGetSymbolAddress((void**)&wk, g_wk);
    cudaGetSymbolAddress((void**)&wv, g_wv);
    cudaGetSymbolAddress((void**)&wo, g_wo);
    cudaGetSymbolAddress((void**)&q, g_q);
    cudaGetSymbolAddress((void**)&k, g_k);
    cudaGetSymbolAddress((void**)&v, g_v);
    cudaGetSymbolAddress((void**)&attn, g_attn);

    cudaFuncSetAttribute(gemm_tf32, cudaFuncAttributeMaxDynamicSharedMemorySize, GEMM_SMEM);
    cudaFuncSetAttribute(attn_tf32, cudaFuncAttributeMaxDynamicSharedMemorySize, ATT_SMEM);

    const int NX = ROWS * D_MODEL, NW = D_MODEL * D_MODEL, NKV = D_MODEL * KV_COLS;
    round_tf32_kernel<<<(NX + 255) / 256, 256>>>(x, xr, NX);
    round_tf32_kernel<<<(NW + 255) / 256, 256>>>(Wq, wq, NW);
    round_tf32_kernel<<<(NKV + 255) / 256, 256>>>(Wk, wk, NKV);
    round_tf32_kernel<<<(NKV + 255) / 256, 256>>>(Wv, wv, NKV);
    round_tf32_kernel<<<(NW + 255) / 256, 256>>>(Wo, wo, NW);

    gemm_tf32<<<dim3(D_MODEL / 128, ROWS / 128), 128, GEMM_SMEM>>>(
        xr, wq, bq, q, ROWS, D_MODEL, D_MODEL, 1);
    gemm_tf32<<<dim3(KV_COLS / 128, ROWS / 128), 128, GEMM_SMEM>>>(
        xr, wk, bk, k, ROWS, KV_COLS, D_MODEL, 1);
    gemm_tf32<<<dim3(KV_COLS / 128, ROWS / 128), 128, GEMM_SMEM>>>(
        xr, wv, bv, v, ROWS, KV_COLS, D_MODEL, 1);

    attn_tf32<<<dim3(SEQ / 64, BATCH * NUM_HEADS), 256, ATT_SMEM>>>(q, k, v, attn);

    gemm_tf32<<<dim3(D_MODEL / 128, ROWS / 128), 128, GEMM_SMEM>>>(
        attn, wo, bo, out, ROWS, D_MODEL, D_MODEL, 0);
}

// round 5
// speedup vs baseline: 10.4622x; 1.6248x over previous
#include <cuda_runtime.h>
#include <cuda_fp16.h>
#include <cstdint>
#include <cstddef>

#define D_MODEL   2048
#define NUM_HEADS 16
#define QGROUPS   4
#define HEAD_DIM  128
#define BATCH     2
#define SEQ       2048
#define ROWS      (BATCH * SEQ)
#define KV_COLS   (QGROUPS * HEAD_DIM)

// ---------------- scratch (half precision) ----------------
__device__ __half g_xh[ROWS * D_MODEL];
__device__ __half g_wqt[D_MODEL * D_MODEL];   // [N][K]
__device__ __half g_wkt[KV_COLS * D_MODEL];
__device__ __half g_wvt[KV_COLS * D_MODEL];
__device__ __half g_wot[D_MODEL * D_MODEL];
__device__ __half g_qh[ROWS * D_MODEL];
__device__ __half g_kh[ROWS * KV_COLS];
__device__ __half g_vh[ROWS * KV_COLS];
__device__ __half g_attnh[ROWS * D_MODEL];

// ---------------- helpers ----------------
__device__ __forceinline__ void mma16(float* d, const uint32_t* a, const uint32_t* b) {
    asm volatile(
        "mma.sync.aligned.m16n8k16.row.col.f32.f16.f16.f32 "
        "{%0,%1,%2,%3}, {%4,%5,%6,%7}, {%8,%9}, {%0,%1,%2,%3};\n"
        : "+f"(d[0]), "+f"(d[1]), "+f"(d[2]), "+f"(d[3])
        : "r"(a[0]), "r"(a[1]), "r"(a[2]), "r"(a[3]), "r"(b[0]), "r"(b[1]));
}
__device__ __forceinline__ void cp16(void* smem, const void* gmem) {
    uint32_t s = (uint32_t)__cvta_generic_to_shared(smem);
    asm volatile("cp.async.cg.shared.global [%0], [%1], 16;\n" :: "r"(s), "l"(gmem));
}
__device__ __forceinline__ void cp_commit() { asm volatile("cp.async.commit_group;\n"); }
template<int N> __device__ __forceinline__ void cp_wait() {
    asm volatile("cp.async.wait_group %0;\n" :: "n"(N));
}
__device__ __forceinline__ uint32_t ldu32(const __half* p) {
    return *(const uint32_t*)p;
}
__device__ __forceinline__ uint32_t packh2(__half a, __half b) {
    __half2 h = __halves2half2(a, b);
    return *(uint32_t*)&h;
}

// ---------------- prepass ----------------
__global__ void f2h_kernel(const float* __restrict__ in, __half* __restrict__ out, int n) {
    int i = blockIdx.x * blockDim.x + threadIdx.x;
    if (i < n) out[i] = __float2half_rn(in[i]);
}
// in [K][N] float -> out [N][K] half, scaled
__global__ void transpose_f2h(const float* __restrict__ in, __half* __restrict__ out,
                              int K, int N, float scale) {
    __shared__ float t[32][33];
    const int k0 = blockIdx.y * 32, n0 = blockIdx.x * 32;
    const int tx = threadIdx.x, ty = threadIdx.y;
    #pragma unroll
    for (int i = 0; i < 32; i += 8)
        t[ty + i][tx] = in[(size_t)(k0 + ty + i) * N + n0 + tx];
    __syncthreads();
    #pragma unroll
    for (int i = 0; i < 32; i += 8)
        out[(size_t)(n0 + ty + i) * K + k0 + tx] = __float2half_rn(t[tx][ty + i] * scale);
}

// ============================================================================
// fp16 GEMM: C[M,N] = A[M,K] @ Bt[N,K]^T + bias*bscale
// CTA 128x128, 256 thr, 8 warps (2x4), warp tile 64x32, BK=32, 2-stage cp.async
// ============================================================================
#define GST (128 * 40)   // halfs per stage per matrix

__global__ __launch_bounds__(256) void gemm_h(
    const __half* __restrict__ A, const __half* __restrict__ Bt,
    const float* __restrict__ bias, float bscale,
    float* __restrict__ Cf, __half* __restrict__ Ch,
    int M, int N, int K)
{
    __shared__ __half As[2][GST];
    __shared__ __half Bs[2][GST];

    const int tid = threadIdx.x, lane = tid & 31, wid = tid >> 5;
    const int gr = lane >> 2, tig = lane & 3;
    const int wm = wid >> 2, wn = wid & 3;
    const int brow = blockIdx.y * 128, bcol = blockIdx.x * 128;

    const int lrow = tid >> 1, lcol = (tid & 1) * 16;
    const __half* gA = A + (size_t)(brow + lrow) * K + lcol;
    const __half* gB = Bt + (size_t)(bcol + lrow) * K + lcol;

    float acc[4][4][4];
    #pragma unroll
    for (int i = 0; i < 4; i++)
        #pragma unroll
        for (int j = 0; j < 4; j++)
            #pragma unroll
            for (int q = 0; q < 4; q++) acc[i][j][q] = 0.f;

    const int NIT = K >> 5;

    // prefetch stage 0
    cp16(&As[0][lrow * 40 + lcol], gA);
    cp16(&As[0][lrow * 40 + lcol + 8], gA + 8);
    cp16(&Bs[0][lrow * 40 + lcol], gB);
    cp16(&Bs[0][lrow * 40 + lcol + 8], gB + 8);
    cp_commit();

    for (int it = 0; it < NIT; it++) {
        if (it + 1 < NIT) {
            const int st = (it + 1) & 1, k0 = (it + 1) * 32;
            cp16(&As[st][lrow * 40 + lcol], gA + k0);
            cp16(&As[st][lrow * 40 + lcol + 8], gA + k0 + 8);
            cp16(&Bs[st][lrow * 40 + lcol], gB + k0);
            cp16(&Bs[st][lrow * 40 + lcol + 8], gB + k0 + 8);
            cp_commit();
            cp_wait<1>();
        } else {
            cp_wait<0>();
        }
        __syncthreads();

        const __half* as = As[it & 1];
        const __half* bs = Bs[it & 1];
        #pragma unroll
        for (int kh = 0; kh < 2; kh++) {
            const int k0 = kh * 16 + 2 * tig;
            uint32_t af[4][4], bf[4][2];
            #pragma unroll
            for (int mt = 0; mt < 4; mt++) {
                const int base = (wm * 64 + mt * 16 + gr) * 40 + k0;
                af[mt][0] = ldu32(&as[base]);
                af[mt][1] = ldu32(&as[base + 8 * 40]);
                af[mt][2] = ldu32(&as[base + 8]);
                af[mt][3] = ldu32(&as[base + 8 * 40 + 8]);
            }
            #pragma unroll
            for (int nt = 0; nt < 4; nt++) {
                const int bb = (wn * 32 + nt * 8 + gr) * 40 + k0;
                bf[nt][0] = ldu32(&bs[bb]);
                bf[nt][1] = ldu32(&bs[bb + 8]);
            }
            #pragma unroll
            for (int mt = 0; mt < 4; mt++)
                #pragma unroll
                for (int nt = 0; nt < 4; nt++)
                    mma16(acc[mt][nt], af[mt], bf[nt]);
        }
        __syncthreads();
    }

    // epilogue
    #pragma unroll
    for (int mt = 0; mt < 4; mt++) {
        const int r0 = brow + wm * 64 + mt * 16 + gr;
        #pragma unroll
        for (int nt = 0; nt < 4; nt++) {
            const int c = bcol + wn * 32 + nt * 8 + 2 * tig;
            const float b0 = bias[c] * bscale, b1 = bias[c + 1] * bscale;
            const float v0 = acc[mt][nt][0] + b0, v1 = acc[mt][nt][1] + b1;
            const float v2 = acc[mt][nt][2] + b0, v3 = acc[mt][nt][3] + b1;
            if (Cf) {
                float2 p0; p0.x = v0; p0.y = v1;
                float2 p1; p1.x = v2; p1.y = v3;
                *(float2*)&Cf[(size_t)r0 * N + c] = p0;
                *(float2*)&Cf[(size_t)(r0 + 8) * N + c] = p1;
            } else {
                *(uint32_t*)&Ch[(size_t)r0 * N + c] = packh2(__float2half_rn(v0), __float2half_rn(v1));
                *(uint32_t*)&Ch[(size_t)(r0 + 8) * N + c] = packh2(__float2half_rn(v2), __float2half_rn(v3));
            }
        }
    }
}

// ============================================================================
// Flash attention fp16 mma. Br=Bc=64, HD=128, 8 warps (wm 0..1 x wn 0..3).
// S warp tile 32x16 (fp32 in smem for softmax); PV warp tile 32x32.
// ============================================================================
#define AQ_OFF 0
#define AK_OFF 17408
#define AV_OFF 34816
#define AP_OFF 52224
#define AS_OFF 61440
#define AM_OFF 78848
#define AL_OFF 79104
#define AC_OFF 79360
#define ATT_SMEM 79616

__global__ __launch_bounds__(256) void attn_h(
    const __half* __restrict__ Q, const __half* __restrict__ Kg,
    const __half* __restrict__ Vg, __half* __restrict__ O)
{
    extern __shared__ char smc[];
    __half* Qs = (__half*)(smc + AQ_OFF);   // [64][136]
    __half* Ks = (__half*)(smc + AK_OFF);   // [64][136]
    __half* Vs = (__half*)(smc + AV_OFF);   // [64][136]
    __half* Ps = (__half*)(smc + AP_OFF);   // [64][72]
    float*  Ss = (float*)(smc + AS_OFF);    // [64][68]
    float*  m_s = (float*)(smc + AM_OFF);
    float*  l_s = (float*)(smc + AL_OFF);
    float*  cr_s = (float*)(smc + AC_OFF);

    const int tid = threadIdx.x, lane = tid & 31, wid = tid >> 5;
    const int gr = lane >> 2, tig = lane & 3;
    const int wm = wid >> 2, wn = wid & 3;
    const int bh = blockIdx.y;
    const int b = bh >> 4, h = bh & 15, g = h >> 2;
    const int q0 = blockIdx.x * 64;

    const int r_ld = tid >> 2, c_ld = (tid & 3) * 32;

    // Q tile cp.async (already scaled by 1/sqrt(hd) at projection time)
    {
        const __half* qp = Q + (size_t)(b * SEQ + q0 + r_ld) * D_MODEL + h * HEAD_DIM + c_ld;
        __half* qs = &Qs[r_ld * 136 + c_ld];
        cp16(qs, qp); cp16(qs + 8, qp + 8); cp16(qs + 16, qp + 16); cp16(qs + 24, qp + 24);
        cp_commit();
    }
    if (tid < 64) { m_s[tid] = -1e30f; l_s[tid] = 0.f; }

    float oacc[2][4][4];
    #pragma unroll
    for (int i = 0; i < 2; i++)
        #pragma unroll
        for (int j = 0; j < 4; j++)
            #pragma unroll
            for (int q = 0; q < 4; q++) oacc[i][j][q] = 0.f;

    const int srow = tid >> 2, scol0 = (tid & 3) * 16;

    for (int s0 = 0; s0 < SEQ; s0 += 64) {
        __syncthreads();
        // K,V tiles
        {
            const __half* kp = Kg + (size_t)(b * SEQ + s0 + r_ld) * KV_COLS + g * HEAD_DIM + c_ld;
            const __half* vp = Vg + (size_t)(b * SEQ + s0 + r_ld) * KV_COLS + g * HEAD_DIM + c_ld;
            __half* ks = &Ks[r_ld * 136 + c_ld];
            __half* vs = &Vs[r_ld * 136 + c_ld];
            cp16(ks, kp); cp16(ks + 8, kp + 8); cp16(ks + 16, kp + 16); cp16(ks + 24, kp + 24);
            cp16(vs, vp); cp16(vs + 8, vp + 8); cp16(vs + 16, vp + 16); cp16(vs + 24, vp + 24);
            cp_commit(); cp_wait<0>();
        }
        __syncthreads();

        // S = Q @ K^T : warp tile 32x16, 8 k-steps
        float sacc[2][2][4];
        #pragma unroll
        for (int i = 0; i < 2; i++)
            #pragma unroll
            for (int j = 0; j < 2; j++)
                #pragma unroll
                for (int q = 0; q < 4; q++) sacc[i][j][q] = 0.f;
        #pragma unroll
        for (int ks = 0; ks < 8; ks++) {
            const int k0 = ks * 16 + 2 * tig;
            uint32_t af[2][4], bf[2][2];
            #pragma unroll
            for (int mt = 0; mt < 2; mt++) {
                const int base = (wm * 32 + mt * 16 + gr) * 136 + k0;
                af[mt][0] = ldu32(&Qs[base]);
                af[mt][1] = ldu32(&Qs[base + 8 * 136]);
                af[mt][2] = ldu32(&Qs[base + 8]);
                af[mt][3] = ldu32(&Qs[base + 8 * 136 + 8]);
            }
            #pragma unroll
            for (int nt = 0; nt < 2; nt++) {
                const int bb = (wn * 16 + nt * 8 + gr) * 136 + k0;
                bf[nt][0] = ldu32(&Ks[bb]);
                bf[nt][1] = ldu32(&Ks[bb + 8]);
            }
            #pragma unroll
            for (int mt = 0; mt < 2; mt++)
                #pragma unroll
                for (int nt = 0; nt < 2; nt++)
                    mma16(sacc[mt][nt], af[mt], bf[nt]);
        }
        #pragma unroll
        for (int mt = 0; mt < 2; mt++) {
            const int r = wm * 32 + mt * 16 + gr;
            #pragma unroll
            for (int nt = 0; nt < 2; nt++) {
                const int c = wn * 16 + nt * 8 + 2 * tig;
                Ss[r * 68 + c] = sacc[mt][nt][0];
                Ss[r * 68 + c + 1] = sacc[mt][nt][1];
                Ss[(r + 8) * 68 + c] = sacc[mt][nt][2];
                Ss[(r + 8) * 68 + c + 1] = sacc[mt][nt][3];
            }
        }
        __syncthreads();

        // online softmax
        {
            float* srw = &Ss[srow * 68 + scol0];
            __half* prw = &Ps[srow * 72 + scol0];
            float tmax = -1e30f;
            #pragma unroll
            for (int j = 0; j < 16; j++) tmax = fmaxf(tmax, srw[j]);
            tmax = fmaxf(tmax, __shfl_xor_sync(0xffffffffu, tmax, 1));
            tmax = fmaxf(tmax, __shfl_xor_sync(0xffffffffu, tmax, 2));
            const float mold = m_s[srow];
            const float mnew = fmaxf(mold, tmax);
            const float corr = __expf(mold - mnew);
            float psum = 0.f;
            #pragma unroll
            for (int j = 0; j < 16; j++) {
                float p = __expf(srw[j] - mnew);
                prw[j] = __float2half_rn(p);
                psum += p;
            }
            psum += __shfl_xor_sync(0xffffffffu, psum, 1);
            psum += __shfl_xor_sync(0xffffffffu, psum, 2);
            if ((tid & 3) == 0) {
                m_s[srow] = mnew;
                cr_s[srow] = corr;
                l_s[srow] = l_s[srow] * corr + psum;
            }
        }
        __syncthreads();

        // rescale O, then O += P @ V : warp tile 32x32, 4 k-steps
        #pragma unroll
        for (int mt = 0; mt < 2; mt++) {
            const float c0 = cr_s[wm * 32 + mt * 16 + gr];
            const float c1 = cr_s[wm * 32 + mt * 16 + gr + 8];
            #pragma unroll
            for (int nt = 0; nt < 4; nt++) {
                oacc[mt][nt][0] *= c0; oacc[mt][nt][1] *= c0;
                oacc[mt][nt][2] *= c1; oacc[mt][nt][3] *= c1;
            }
        }
        #pragma unroll
        for (int ks = 0; ks < 4; ks++) {
            const int k0 = ks * 16 + 2 * tig;
            uint32_t af[2][4], bf[4][2];
            #pragma unroll
            for (int mt = 0; mt < 2; mt++) {
                const int base = (wm * 32 + mt * 16 + gr) * 72 + k0;
                af[mt][0] = ldu32(&Ps[base]);
                af[mt][1] = ldu32(&Ps[base + 8 * 72]);
                af[mt][2] = ldu32(&Ps[base + 8]);
                af[mt][3] = ldu32(&Ps[base + 8 * 72 + 8]);
            }
            #pragma unroll
            for (int nt = 0; nt < 4; nt++) {
                const int n = wn * 32 + nt * 8 + gr;
                bf[nt][0] = packh2(Vs[k0 * 136 + n], Vs[(k0 + 1) * 136 + n]);
                bf[nt][1] = packh2(Vs[(k0 + 8) * 136 + n], Vs[(k0 + 9) * 136 + n]);
            }
            #pragma unroll
            for (int mt = 0; mt < 2; mt++)
                #pragma unroll
                for (int nt = 0; nt < 4; nt++)
                    mma16(oacc[mt][nt], af[mt], bf[nt]);
        }
    }

    // finalize: O = oacc / l  -> half
    #pragma unroll
    for (int mt = 0; mt < 2; mt++) {
        const int r = wm * 32 + mt * 16 + gr;
        const float il0 = 1.f / l_s[r], il1 = 1.f / l_s[r + 8];
        __half* o0 = O + (size_t)(b * SEQ + q0 + r) * D_MODEL + h * HEAD_DIM;
        __half* o1 = O + (size_t)(b * SEQ + q0 + r + 8) * D_MODEL + h * HEAD_DIM;
        #pragma unroll
        for (int nt = 0; nt < 4; nt++) {
            const int c = wn * 32 + nt * 8 + 2 * tig;
            *(uint32_t*)&o0[c] = packh2(__float2half_rn(oacc[mt][nt][0] * il0),
                                        __float2half_rn(oacc[mt][nt][1] * il0));
            *(uint32_t*)&o1[c] = packh2(__float2half_rn(oacc[mt][nt][2] * il1),
                                        __float2half_rn(oacc[mt][nt][3] * il1));
        }
    }
}

// ============================================================================
extern "C" void kernel_launch(void* const* d_in, const int* in_sizes, int n_in,
                              void* d_out, int out_size)
{
    const float* x  = (const float*)d_in[0];
    const float* Wq = (const float*)d_in[1];
    const float* bq = (const float*)d_in[2];
    const float* Wk = (const float*)d_in[3];
    const float* bk = (const float*)d_in[4];
    const float* Wv = (const float*)d_in[5];
    const float* bv = (const float*)d_in[6];
    const float* Wo = (const float*)d_in[7];
    const float* bo = (const float*)d_in[8];
    float* out = (float*)d_out;

    __half *xh, *wqt, *wkt, *wvt, *wot, *qh, *kh, *vh, *attnh;
    cudaGetSymbolAddress((void**)&xh, g_xh);
    cudaGetSymbolAddress((void**)&wqt, g_wqt);
    cudaGetSymbolAddress((void**)&wkt, g_wkt);
    cudaGetSymbolAddress((void**)&wvt, g_wvt);
    cudaGetSymbolAddress((void**)&wot, g_wot);
    cudaGetSymbolAddress((void**)&qh, g_qh);
    cudaGetSymbolAddress((void**)&kh, g_kh);
    cudaGetSymbolAddress((void**)&vh, g_vh);
    cudaGetSymbolAddress((void**)&attnh, g_attnh);

    cudaFuncSetAttribute(attn_h, cudaFuncAttributeMaxDynamicSharedMemorySize, ATT_SMEM);

    const float qscale = 0.08838834764831845f;  // 1/sqrt(128)
    const int NX = ROWS * D_MODEL;

    f2h_kernel<<<(NX + 255) / 256, 256>>>(x, xh, NX);
    transpose_f2h<<<dim3(D_MODEL / 32, D_MODEL / 32), dim3(32, 8)>>>(Wq, wqt, D_MODEL, D_MODEL, qscale);
    transpose_f2h<<<dim3(KV_COLS / 32, D_MODEL / 32), dim3(32, 8)>>>(Wk, wkt, D_MODEL, KV_COLS, 1.0f);
    transpose_f2h<<<dim3(KV_COLS / 32, D_MODEL / 32), dim3(32, 8)>>>(Wv, wvt, D_MODEL, KV_COLS, 1.0f);
    transpose_f2h<<<dim3(D_MODEL / 32, D_MODEL / 32), dim3(32, 8)>>>(Wo, wot, D_MODEL, D_MODEL, 1.0f);

    gemm_h<<<dim3(D_MODEL / 128, ROWS / 128), 256>>>(
        xh, wqt, bq, qscale, nullptr, qh, ROWS, D_MODEL, D_MODEL);
    gemm_h<<<dim3(KV_COLS / 128, ROWS / 128), 256>>>(
        xh, wkt, bk, 1.0f, nullptr, kh, ROWS, KV_COLS, D_MODEL);
    gemm_h<<<dim3(KV_COLS / 128, ROWS / 128), 256>>>(
        xh, wvt, bv, 1.0f, nullptr, vh, ROWS, KV_COLS, D_MODEL);

    attn_h<<<dim3(SEQ / 64, BATCH * NUM_HEADS), 256, ATT_SMEM>>>(qh, kh, vh, attnh);

    gemm_h<<<dim3(D_MODEL / 128, ROWS / 128), 256>>>(
        attnh, wot, bo, 1.0f, out, nullptr, ROWS, D_MODEL, D_MODEL);
}

// round 6
// speedup vs baseline: 10.8640x; 1.0384x over previous
#include <cuda_runtime.h>
#include <cuda_fp16.h>
#include <cstdint>
#include <cstddef>

#define D_MODEL   2048
#define NUM_HEADS 16
#define QGROUPS   4
#define HEAD_DIM  128
#define BATCH     2
#define SEQ       2048
#define ROWS      (BATCH * SEQ)
#define KV_COLS   (QGROUPS * HEAD_DIM)
#define QKV_LD    3072      // packed q(2048) | k(512) | v(512)

// ---------------- scratch ----------------
__device__ __half g_xh[ROWS * D_MODEL];
__device__ __half g_wqkvt[QKV_LD * D_MODEL];   // rows: Wq^T(2048) Wk^T(512) Wv^T(512)
__device__ float  g_bqkv[QKV_LD];
__device__ __half g_wot[D_MODEL * D_MODEL];
__device__ __half g_qkvh[ROWS * QKV_LD];
__device__ __half g_attnh[ROWS * D_MODEL];

// ---------------- helpers ----------------
__device__ __forceinline__ void mma16(float* d, const uint32_t* a, const uint32_t* b) {
    asm volatile(
        "mma.sync.aligned.m16n8k16.row.col.f32.f16.f16.f32 "
        "{%0,%1,%2,%3}, {%4,%5,%6,%7}, {%8,%9}, {%0,%1,%2,%3};\n"
        : "+f"(d[0]), "+f"(d[1]), "+f"(d[2]), "+f"(d[3])
        : "r"(a[0]), "r"(a[1]), "r"(a[2]), "r"(a[3]), "r"(b[0]), "r"(b[1]));
}
__device__ __forceinline__ void ldm_x4(uint32_t* r, uint32_t a) {
    asm volatile("ldmatrix.sync.aligned.m8n8.x4.shared.b16 {%0,%1,%2,%3}, [%4];"
                 : "=r"(r[0]), "=r"(r[1]), "=r"(r[2]), "=r"(r[3]) : "r"(a));
}
__device__ __forceinline__ void ldm_x4t(uint32_t* r, uint32_t a) {
    asm volatile("ldmatrix.sync.aligned.m8n8.x4.trans.shared.b16 {%0,%1,%2,%3}, [%4];"
                 : "=r"(r[0]), "=r"(r[1]), "=r"(r[2]), "=r"(r[3]) : "r"(a));
}
__device__ __forceinline__ void cp16(void* smem, const void* gmem) {
    uint32_t s = (uint32_t)__cvta_generic_to_shared(smem);
    asm volatile("cp.async.cg.shared.global [%0], [%1], 16;\n" :: "r"(s), "l"(gmem));
}
__device__ __forceinline__ void cp_commit() { asm volatile("cp.async.commit_group;\n"); }
template<int N> __device__ __forceinline__ void cp_wait() {
    asm volatile("cp.async.wait_group %0;\n" :: "n"(N));
}
__device__ __forceinline__ uint32_t sm_u32(const void* p) {
    return (uint32_t)__cvta_generic_to_shared(p);
}
__device__ __forceinline__ uint32_t packh2(float a, float b) {
    __half2 h = __halves2half2(__float2half_rn(a), __float2half_rn(b));
    return *(uint32_t*)&h;
}

// ---------------- prepass ----------------
__global__ void f2h_kernel(const float* __restrict__ in, __half* __restrict__ out, int n) {
    int i = blockIdx.x * blockDim.x + threadIdx.x;
    if (i < n) out[i] = __float2half_rn(in[i]);
}
__global__ void transpose_f2h(const float* __restrict__ in, __half* __restrict__ out,
                              int K, int N, float scale) {
    __shared__ float t[32][33];
    const int k0 = blockIdx.y * 32, n0 = blockIdx.x * 32;
    const int tx = threadIdx.x, ty = threadIdx.y;
    #pragma unroll
    for (int i = 0; i < 32; i += 8)
        t[ty + i][tx] = in[(size_t)(k0 + ty + i) * N + n0 + tx];
    __syncthreads();
    #pragma unroll
    for (int i = 0; i < 32; i += 8)
        out[(size_t)(n0 + ty + i) * K + k0 + tx] = __float2half_rn(t[tx][ty + i] * scale);
}
__global__ void concat_bias(const float* __restrict__ bq, const float* __restrict__ bk,
                            const float* __restrict__ bv, float* __restrict__ out) {
    const float qscale = 0.08838834764831845f;
    int i = blockIdx.x * blockDim.x + threadIdx.x;
    if (i < 2048)      out[i] = bq[i] * qscale;
    else if (i < 2560) out[i] = bk[i - 2048];
    else if (i < 3072) out[i] = bv[i - 2560];
}

// ============================================================================
// fp16 GEMM: C[M,N] = A[M,K] @ Bt[N,K]^T + bias
// CTA 128x256, 256 thr, 8 warps (2x4), warp tile 64x64, BK=32, 2-stage cp.async,
// ldmatrix fragment loads. smem stride 40 halfs (conflict-free).
// ============================================================================
#define GEMM_SMEM 61440   // 2*10240 (A) + 2*20480 (B)

__global__ __launch_bounds__(256) void gemm_h(
    const __half* __restrict__ A, const __half* __restrict__ Bt,
    const float* __restrict__ bias,
    float* __restrict__ Cf, __half* __restrict__ Ch,
    int M, int N, int K)
{
    extern __shared__ char smc[];
    __half* As0 = (__half*)smc;
    __half* As1 = (__half*)(smc + 10240);
    __half* Bs0 = (__half*)(smc + 20480);
    __half* Bs1 = (__half*)(smc + 40960);

    const int tid = threadIdx.x, lane = tid & 31, wid = tid >> 5;
    const int gr = lane >> 2, tig = lane & 3;
    const int wm = wid >> 2, wn = wid & 3;
    const int brow = blockIdx.y * 128, bcol = blockIdx.x * 256;

    const int arow = tid >> 1, acol = (tid & 1) * 16;
    const __half* gA = A + (size_t)(brow + arow) * K + acol;
    const __half* gB = Bt + (size_t)(bcol + tid) * K;

    // ldmatrix per-lane offsets (halfs)
    const int aoff = (wm * 64 + (lane & 7) + ((lane >> 3) & 1) * 8) * 40 + (lane >> 4) * 8;
    const int boff = (wn * 64 + (lane & 7) + (lane >> 4) * 8) * 40 + ((lane >> 3) & 1) * 8;

    float acc[4][8][4] = {};
    const int NIT = K >> 5;

    // prefetch stage 0
    {
        cp16(&As0[arow * 40 + acol], gA);
        cp16(&As0[arow * 40 + acol + 8], gA + 8);
        __half* bb = &Bs0[tid * 40];
        cp16(bb, gB); cp16(bb + 8, gB + 8); cp16(bb + 16, gB + 16); cp16(bb + 24, gB + 24);
        cp_commit();
    }

    for (int it = 0; it < NIT; it++) {
        if (it + 1 < NIT) {
            const int k0 = (it + 1) * 32;
            __half* a = ((it + 1) & 1) ? As1 : As0;
            __half* b = ((it + 1) & 1) ? Bs1 : Bs0;
            cp16(&a[arow * 40 + acol], gA + k0);
            cp16(&a[arow * 40 + acol + 8], gA + k0 + 8);
            __half* bb = &b[tid * 40];
            cp16(bb, gB + k0); cp16(bb + 8, gB + k0 + 8);
            cp16(bb + 16, gB + k0 + 16); cp16(bb + 24, gB + k0 + 24);
            cp_commit();
            cp_wait<1>();
        } else {
            cp_wait<0>();
        }
        __syncthreads();

        const __half* a = (it & 1) ? As1 : As0;
        const __half* b = (it & 1) ? Bs1 : Bs0;
        const uint32_t aaddr = sm_u32(a) + 2u * aoff;
        const uint32_t baddr = sm_u32(b) + 2u * boff;

        #pragma unroll
        for (int ks = 0; ks < 2; ks++) {
            uint32_t af[4][4];
            #pragma unroll
            for (int mt = 0; mt < 4; mt++)
                ldm_x4(af[mt], aaddr + mt * 1280 + ks * 32);
            #pragma unroll
            for (int ntp = 0; ntp < 4; ntp++) {
                uint32_t bf[4];
                ldm_x4(bf, baddr + ntp * 1280 + ks * 32);
                #pragma unroll
                for (int mt = 0; mt < 4; mt++) {
                    mma16(acc[mt][2 * ntp], af[mt], bf);
                    mma16(acc[mt][2 * ntp + 1], af[mt], bf + 2);
                }
            }
        }
        __syncthreads();
    }

    // epilogue
    #pragma unroll
    for (int mt = 0; mt < 4; mt++) {
        const int r0 = brow + wm * 64 + mt * 16 + gr;
        #pragma unroll
        for (int nt = 0; nt < 8; nt++) {
            const int c = bcol + wn * 64 + nt * 8 + 2 * tig;
            const float b0 = bias[c], b1 = bias[c + 1];
            const float v0 = acc[mt][nt][0] + b0, v1 = acc[mt][nt][1] + b1;
            const float v2 = acc[mt][nt][2] + b0, v3 = acc[mt][nt][3] + b1;
            if (Cf) {
                float2 p0; p0.x = v0; p0.y = v1;
                float2 p1; p1.x = v2; p1.y = v3;
                *(float2*)&Cf[(size_t)r0 * N + c] = p0;
                *(float2*)&Cf[(size_t)(r0 + 8) * N + c] = p1;
            } else {
                *(uint32_t*)&Ch[(size_t)r0 * N + c] = packh2(v0, v1);
                *(uint32_t*)&Ch[(size_t)(r0 + 8) * N + c] = packh2(v2, v3);
            }
        }
    }
}

// ============================================================================
// Flash attention fp16, ldmatrix fragments (incl. .trans for V), double-
// buffered K/V cp.async prefetch. Br=Bc=64, 8 warps.
// Reads packed QKV [ROWS][3072]; writes attnh [ROWS][2048].
// ============================================================================
#define AQ   0
#define AK   17408
#define AV   (AK + 2 * 17408)
#define AP   (AV + 2 * 17408)
#define ASS  (AP + 9216)
#define AMM  (ASS + 17408)
#define ALL  (AMM + 256)
#define ACR  (ALL + 256)
#define ATT_SMEM (ACR + 256)   // 114688-ish

__global__ __launch_bounds__(256) void attn_h(
    const __half* __restrict__ QKV, __half* __restrict__ O)
{
    extern __shared__ char smc[];
    __half* Qs  = (__half*)(smc + AQ);        // [64][136]
    __half* Ks0 = (__half*)(smc + AK);
    __half* Ks1 = (__half*)(smc + AK + 17408);
    __half* Vs0 = (__half*)(smc + AV);
    __half* Vs1 = (__half*)(smc + AV + 17408);
    __half* Ps  = (__half*)(smc + AP);        // [64][72]
    float*  Ss  = (float*)(smc + ASS);        // [64][68]
    float*  m_s = (float*)(smc + AMM);
    float*  l_s = (float*)(smc + ALL);
    float*  cr_s = (float*)(smc + ACR);

    const int tid = threadIdx.x, lane = tid & 31, wid = tid >> 5;
    const int gr = lane >> 2, tig = lane & 3;
    const int wm = wid >> 2, wn = wid & 3;
    const int bh = blockIdx.y;
    const int b = bh >> 4, h = bh & 15, g = h >> 2;
    const int q0 = blockIdx.x * 64;

    const int r_ld = tid >> 2, c_ld = (tid & 3) * 32;
    const size_t rowbase = (size_t)b * SEQ * QKV_LD;

    // Q tile (scale folded into projection)
    {
        const __half* qp = QKV + rowbase + (size_t)(q0 + r_ld) * QKV_LD + h * HEAD_DIM + c_ld;
        __half* qs = &Qs[r_ld * 136 + c_ld];
        cp16(qs, qp); cp16(qs + 8, qp + 8); cp16(qs + 16, qp + 16); cp16(qs + 24, qp + 24);
    }
    // K/V tile 0 -> buf 0 (same commit group as Q)
    {
        const __half* kp = QKV + rowbase + (size_t)r_ld * QKV_LD + 2048 + g * HEAD_DIM + c_ld;
        const __half* vp = kp + 512;
        __half* ks = &Ks0[r_ld * 136 + c_ld];
        __half* vs = &Vs0[r_ld * 136 + c_ld];
        cp16(ks, kp); cp16(ks + 8, kp + 8); cp16(ks + 16, kp + 16); cp16(ks + 24, kp + 24);
        cp16(vs, vp); cp16(vs + 8, vp + 8); cp16(vs + 16, vp + 16); cp16(vs + 24, vp + 24);
        cp_commit();
    }
    if (tid < 64) { m_s[tid] = -1e30f; l_s[tid] = 0.f; }

    float oacc[2][4][4] = {};

    // ldmatrix per-lane offsets (halfs)
    const int qa_off = (wm * 32 + (lane & 7) + ((lane >> 3) & 1) * 8) * 136 + (lane >> 4) * 8;
    const int kb_off = (wn * 16 + (lane & 7) + (lane >> 4) * 8) * 136 + ((lane >> 3) & 1) * 8;
    const int pa_off = (wm * 32 + (lane & 7) + ((lane >> 3) & 1) * 8) * 72 + (lane >> 4) * 8;
    const int vb_off = ((lane & 7) + ((lane >> 3) & 1) * 8) * 136 + wn * 32 + (lane >> 4) * 8;

    const uint32_t qaddr = sm_u32(Qs) + 2u * qa_off;
    const uint32_t paddr = sm_u32(Ps) + 2u * pa_off;
    const int srow = tid >> 2, scol0 = (tid & 3) * 16;

    for (int it = 0; it < SEQ / 64; it++) {
        const int buf = it & 1;
        // prefetch next K/V into buf^1 (safe: trailing sync of prev iter)
        if (it + 1 < SEQ / 64) {
            const int s0 = (it + 1) * 64;
            const __half* kp = QKV + rowbase + (size_t)(s0 + r_ld) * QKV_LD + 2048 + g * HEAD_DIM + c_ld;
            const __half* vp = kp + 512;
            __half* ks = (buf ? Ks0 : Ks1) + r_ld * 136 + c_ld;
            __half* vs = (buf ? Vs0 : Vs1) + r_ld * 136 + c_ld;
            cp16(ks, kp); cp16(ks + 8, kp + 8); cp16(ks + 16, kp + 16); cp16(ks + 24, kp + 24);
            cp16(vs, vp); cp16(vs + 8, vp + 8); cp16(vs + 16, vp + 16); cp16(vs + 24, vp + 24);
            cp_commit();
            cp_wait<1>();
        } else {
            cp_wait<0>();
        }
        __syncthreads();

        const uint32_t kaddr = sm_u32(buf ? Ks1 : Ks0) + 2u * kb_off;
        const uint32_t vaddr = sm_u32(buf ? Vs1 : Vs0) + 2u * vb_off;

        // ---- S = Q @ K^T (warp tile 32x16) ----
        float sacc[2][2][4] = {};
        #pragma unroll
        for (int ks = 0; ks < 8; ks++) {
            uint32_t af[2][4], bf[4];
            ldm_x4(af[0], qaddr + ks * 32);
            ldm_x4(af[1], qaddr + 16 * 272 + ks * 32);
            ldm_x4(bf, kaddr + ks * 32);
            mma16(sacc[0][0], af[0], bf); mma16(sacc[0][1], af[0], bf + 2);
            mma16(sacc[1][0], af[1], bf); mma16(sacc[1][1], af[1], bf + 2);
        }
        #pragma unroll
        for (int mt = 0; mt < 2; mt++) {
            const int r = wm * 32 + mt * 16 + gr;
            #pragma unroll
            for (int nt = 0; nt < 2; nt++) {
                const int c = wn * 16 + nt * 8 + 2 * tig;
                Ss[r * 68 + c] = sacc[mt][nt][0];
                Ss[r * 68 + c + 1] = sacc[mt][nt][1];
                Ss[(r + 8) * 68 + c] = sacc[mt][nt][2];
                Ss[(r + 8) * 68 + c + 1] = sacc[mt][nt][3];
            }
        }
        __syncthreads();

        // ---- online softmax ----
        {
            float* srw = &Ss[srow * 68 + scol0];
            __half* prw = &Ps[srow * 72 + scol0];
            float tmax = -1e30f;
            #pragma unroll
            for (int j = 0; j < 16; j++) tmax = fmaxf(tmax, srw[j]);
            tmax = fmaxf(tmax, __shfl_xor_sync(0xffffffffu, tmax, 1));
            tmax = fmaxf(tmax, __shfl_xor_sync(0xffffffffu, tmax, 2));
            const float mold = m_s[srow];
            const float mnew = fmaxf(mold, tmax);
            const float corr = __expf(mold - mnew);
            float psum = 0.f;
            #pragma unroll
            for (int j = 0; j < 16; j++) {
                float p = __expf(srw[j] - mnew);
                prw[j] = __float2half_rn(p);
                psum += p;
            }
            psum += __shfl_xor_sync(0xffffffffu, psum, 1);
            psum += __shfl_xor_sync(0xffffffffu, psum, 2);
            if ((tid & 3) == 0) {
                m_s[srow] = mnew;
                cr_s[srow] = corr;
                l_s[srow] = l_s[srow] * corr + psum;
            }
        }
        __syncthreads();

        // ---- rescale O, then O += P @ V (warp tile 32x32) ----
        #pragma unroll
        for (int mt = 0; mt < 2; mt++) {
            const float c0 = cr_s[wm * 32 + mt * 16 + gr];
            const float c1 = cr_s[wm * 32 + mt * 16 + gr + 8];
            #pragma unroll
            for (int nt = 0; nt < 4; nt++) {
                oacc[mt][nt][0] *= c0; oacc[mt][nt][1] *= c0;
                oacc[mt][nt][2] *= c1; oacc[mt][nt][3] *= c1;
            }
        }
        #pragma unroll
        for (int ks = 0; ks < 4; ks++) {
            uint32_t af[2][4];
            ldm_x4(af[0], paddr + ks * 32);
            ldm_x4(af[1], paddr + 16 * 144 + ks * 32);
            #pragma unroll
            for (int ntp = 0; ntp < 2; ntp++) {
                uint32_t bf[4];
                ldm_x4t(bf, vaddr + ks * 16 * 272 + ntp * 32);
                mma16(oacc[0][2 * ntp], af[0], bf); mma16(oacc[0][2 * ntp + 1], af[0], bf + 2);
                mma16(oacc[1][2 * ntp], af[1], bf); mma16(oacc[1][2 * ntp + 1], af[1], bf + 2);
            }
        }
        __syncthreads();   // protect Ss/Ps and K/V buf for next iteration's writes
    }

    // ---- finalize ----
    #pragma unroll
    for (int mt = 0; mt < 2; mt++) {
        const int r = wm * 32 + mt * 16 + gr;
        const float il0 = 1.f / l_s[r], il1 = 1.f / l_s[r + 8];
        __half* o0 = O + (size_t)(b * SEQ + q0 + r) * D_MODEL + h * HEAD_DIM;
        __half* o1 = O + (size_t)(b * SEQ + q0 + r + 8) * D_MODEL + h * HEAD_DIM;
        #pragma unroll
        for (int nt = 0; nt < 4; nt++) {
            const int c = wn * 32 + nt * 8 + 2 * tig;
            *(uint32_t*)&o0[c] = packh2(oacc[mt][nt][0] * il0, oacc[mt][nt][1] * il0);
            *(uint32_t*)&o1[c] = packh2(oacc[mt][nt][2] * il1, oacc[mt][nt][3] * il1);
        }
    }
}

// ============================================================================
extern "C" void kernel_launch(void* const* d_in, const int* in_sizes, int n_in,
                              void* d_out, int out_size)
{
    const float* x  = (const float*)d_in[0];
    const float* Wq = (const float*)d_in[1];
    const float* bq = (const float*)d_in[2];
    const float* Wk = (const float*)d_in[3];
    const float* bk = (const float*)d_in[4];
    const float* Wv = (const float*)d_in[5];
    const float* bv = (const float*)d_in[6];
    const float* Wo = (const float*)d_in[7];
    const float* bo = (const float*)d_in[8];
    float* out = (float*)d_out;

    __half *xh, *wqkvt, *wot, *qkvh, *attnh;
    float *bqkv;
    cudaGetSymbolAddress((void**)&xh, g_xh);
    cudaGetSymbolAddress((void**)&wqkvt, g_wqkvt);
    cudaGetSymbolAddress((void**)&bqkv, g_bqkv);
    cudaGetSymbolAddress((void**)&wot, g_wot);
    cudaGetSymbolAddress((void**)&qkvh, g_qkvh);
    cudaGetSymbolAddress((void**)&attnh, g_attnh);

    cudaFuncSetAttribute(gemm_h, cudaFuncAttributeMaxDynamicSharedMemorySize, GEMM_SMEM);
    cudaFuncSetAttribute(attn_h, cudaFuncAttributeMaxDynamicSharedMemorySize, ATT_SMEM);

    const float qscale = 0.08838834764831845f;  // 1/sqrt(128)
    const int NX = ROWS * D_MODEL;

    f2h_kernel<<<(NX + 255) / 256, 256>>>(x, xh, NX);
    // weights: pre-transpose to [N][K] half, qscale folded into Wq
    transpose_f2h<<<dim3(D_MODEL / 32, D_MODEL / 32), dim3(32, 8)>>>(
        Wq, wqkvt, D_MODEL, D_MODEL, qscale);
    transpose_f2h<<<dim3(KV_COLS / 32, D_MODEL / 32), dim3(32, 8)>>>(
        Wk, wqkvt + 2048 * D_MODEL, D_MODEL, KV_COLS, 1.0f);
    transpose_f2h<<<dim3(KV_COLS / 32, D_MODEL / 32), dim3(32, 8)>>>(
        Wv, wqkvt + 2560 * D_MODEL, D_MODEL, KV_COLS, 1.0f);
    transpose_f2h<<<dim3(D_MODEL / 32, D_MODEL / 32), dim3(32, 8)>>>(
        Wo, wot, D_MODEL, D_MODEL, 1.0f);
    concat_bias<<<QKV_LD / 256, 256>>>(bq, bk, bv, bqkv);

    // fused QKV projection -> packed [ROWS][3072] half
    gemm_h<<<dim3(QKV_LD / 256, ROWS / 128), 256, GEMM_SMEM>>>(
        xh, wqkvt, bqkv, nullptr, qkvh, ROWS, QKV_LD, D_MODEL);

    attn_h<<<dim3(SEQ / 64, BATCH * NUM_HEADS), 256, ATT_SMEM>>>(qkvh, attnh);

    // output projection -> float d_out
    gemm_h<<<dim3(D_MODEL / 256, ROWS / 128), 256, GEMM_SMEM>>>(
        attnh, wot, bo, out, nullptr, ROWS, D_MODEL, D_MODEL);
}

// round 7
// speedup vs baseline: 14.2238x; 1.3093x over previous
#include <cuda_runtime.h>
#include <cuda_fp16.h>
#include <cstdint>
#include <cstddef>

#define D_MODEL   2048
#define NUM_HEADS 16
#define QGROUPS   4
#define HEAD_DIM  128
#define BATCH     2
#define SEQ       2048
#define ROWS      (BATCH * SEQ)
#define KV_COLS   (QGROUPS * HEAD_DIM)
#define QKV_LD    3072      // packed q(2048) | k(512) | v(512)

// ---------------- scratch ----------------
__device__ __half g_xh[ROWS * D_MODEL];
__device__ __half g_wqkvt[QKV_LD * D_MODEL];   // rows: Wq^T(2048) Wk^T(512) Wv^T(512)
__device__ float  g_bqkv[QKV_LD];
__device__ __half g_wot[D_MODEL * D_MODEL];
__device__ __half g_qkvh[ROWS * QKV_LD];
__device__ __half g_attnh[ROWS * D_MODEL];

// ---------------- helpers ----------------
__device__ __forceinline__ void mma16(float* d, const uint32_t* a, const uint32_t* b) {
    asm volatile(
        "mma.sync.aligned.m16n8k16.row.col.f32.f16.f16.f32 "
        "{%0,%1,%2,%3}, {%4,%5,%6,%7}, {%8,%9}, {%0,%1,%2,%3};\n"
        : "+f"(d[0]), "+f"(d[1]), "+f"(d[2]), "+f"(d[3])
        : "r"(a[0]), "r"(a[1]), "r"(a[2]), "r"(a[3]), "r"(b[0]), "r"(b[1]));
}
__device__ __forceinline__ void ldm_x4(uint32_t* r, uint32_t a) {
    asm volatile("ldmatrix.sync.aligned.m8n8.x4.shared.b16 {%0,%1,%2,%3}, [%4];"
                 : "=r"(r[0]), "=r"(r[1]), "=r"(r[2]), "=r"(r[3]) : "r"(a));
}
__device__ __forceinline__ void ldm_x4t(uint32_t* r, uint32_t a) {
    asm volatile("ldmatrix.sync.aligned.m8n8.x4.trans.shared.b16 {%0,%1,%2,%3}, [%4];"
                 : "=r"(r[0]), "=r"(r[1]), "=r"(r[2]), "=r"(r[3]) : "r"(a));
}
__device__ __forceinline__ void cp16(void* smem, const void* gmem) {
    uint32_t s = (uint32_t)__cvta_generic_to_shared(smem);
    asm volatile("cp.async.cg.shared.global [%0], [%1], 16;\n" :: "r"(s), "l"(gmem));
}
__device__ __forceinline__ void cp_commit() { asm volatile("cp.async.commit_group;\n"); }
template<int N> __device__ __forceinline__ void cp_wait() {
    asm volatile("cp.async.wait_group %0;\n" :: "n"(N));
}
__device__ __forceinline__ uint32_t sm_u32(const void* p) {
    return (uint32_t)__cvta_generic_to_shared(p);
}
__device__ __forceinline__ uint32_t packh2(float a, float b) {
    __half2 h = __halves2half2(__float2half_rn(a), __float2half_rn(b));
    return *(uint32_t*)&h;
}

// ---------------- prepass ----------------
__global__ void f2h_kernel(const float* __restrict__ in, __half* __restrict__ out, int n) {
    int i = blockIdx.x * blockDim.x + threadIdx.x;
    if (i < n) out[i] = __float2half_rn(in[i]);
}
__global__ void transpose_f2h(const float* __restrict__ in, __half* __restrict__ out,
                              int K, int N, float scale) {
    __shared__ float t[32][33];
    const int k0 = blockIdx.y * 32, n0 = blockIdx.x * 32;
    const int tx = threadIdx.x, ty = threadIdx.y;
    #pragma unroll
    for (int i = 0; i < 32; i += 8)
        t[ty + i][tx] = in[(size_t)(k0 + ty + i) * N + n0 + tx];
    __syncthreads();
    #pragma unroll
    for (int i = 0; i < 32; i += 8)
        out[(size_t)(n0 + ty + i) * K + k0 + tx] = __float2half_rn(t[tx][ty + i] * scale);
}
__global__ void concat_bias(const float* __restrict__ bq, const float* __restrict__ bk,
                            const float* __restrict__ bv, float* __restrict__ out,
                            float qscale) {
    int i = blockIdx.x * blockDim.x + threadIdx.x;
    if (i < 2048)      out[i] = bq[i] * qscale;
    else if (i < 2560) out[i] = bk[i - 2048];
    else if (i < 3072) out[i] = bv[i - 2560];
}

// ============================================================================
// fp16 GEMM (unchanged from R6): CTA 128x256, 8 warps, 64x64 warp tile,
// BK=32, 2-stage cp.async, ldmatrix.
// ============================================================================
#define GEMM_SMEM 61440

__global__ __launch_bounds__(256) void gemm_h(
    const __half* __restrict__ A, const __half* __restrict__ Bt,
    const float* __restrict__ bias,
    float* __restrict__ Cf, __half* __restrict__ Ch,
    int M, int N, int K)
{
    extern __shared__ char smc[];
    __half* As0 = (__half*)smc;
    __half* As1 = (__half*)(smc + 10240);
    __half* Bs0 = (__half*)(smc + 20480);
    __half* Bs1 = (__half*)(smc + 40960);

    const int tid = threadIdx.x, lane = tid & 31, wid = tid >> 5;
    const int gr = lane >> 2, tig = lane & 3;
    const int wm = wid >> 2, wn = wid & 3;
    const int brow = blockIdx.y * 128, bcol = blockIdx.x * 256;

    const int arow = tid >> 1, acol = (tid & 1) * 16;
    const __half* gA = A + (size_t)(brow + arow) * K + acol;
    const __half* gB = Bt + (size_t)(bcol + tid) * K;

    const int aoff = (wm * 64 + (lane & 7) + ((lane >> 3) & 1) * 8) * 40 + (lane >> 4) * 8;
    const int boff = (wn * 64 + (lane & 7) + (lane >> 4) * 8) * 40 + ((lane >> 3) & 1) * 8;

    float acc[4][8][4] = {};
    const int NIT = K >> 5;

    {
        cp16(&As0[arow * 40 + acol], gA);
        cp16(&As0[arow * 40 + acol + 8], gA + 8);
        __half* bb = &Bs0[tid * 40];
        cp16(bb, gB); cp16(bb + 8, gB + 8); cp16(bb + 16, gB + 16); cp16(bb + 24, gB + 24);
        cp_commit();
    }

    for (int it = 0; it < NIT; it++) {
        if (it + 1 < NIT) {
            const int k0 = (it + 1) * 32;
            __half* a = ((it + 1) & 1) ? As1 : As0;
            __half* b = ((it + 1) & 1) ? Bs1 : Bs0;
            cp16(&a[arow * 40 + acol], gA + k0);
            cp16(&a[arow * 40 + acol + 8], gA + k0 + 8);
            __half* bb = &b[tid * 40];
            cp16(bb, gB + k0); cp16(bb + 8, gB + k0 + 8);
            cp16(bb + 16, gB + k0 + 16); cp16(bb + 24, gB + k0 + 24);
            cp_commit();
            cp_wait<1>();
        } else {
            cp_wait<0>();
        }
        __syncthreads();

        const __half* a = (it & 1) ? As1 : As0;
        const __half* b = (it & 1) ? Bs1 : Bs0;
        const uint32_t aaddr = sm_u32(a) + 2u * aoff;
        const uint32_t baddr = sm_u32(b) + 2u * boff;

        #pragma unroll
        for (int ks = 0; ks < 2; ks++) {
            uint32_t af[4][4];
            #pragma unroll
            for (int mt = 0; mt < 4; mt++)
                ldm_x4(af[mt], aaddr + mt * 1280 + ks * 32);
            #pragma unroll
            for (int ntp = 0; ntp < 4; ntp++) {
                uint32_t bf[4];
                ldm_x4(bf, baddr + ntp * 1280 + ks * 32);
                #pragma unroll
                for (int mt = 0; mt < 4; mt++) {
                    mma16(acc[mt][2 * ntp], af[mt], bf);
                    mma16(acc[mt][2 * ntp + 1], af[mt], bf + 2);
                }
            }
        }
        __syncthreads();
    }

    #pragma unroll
    for (int mt = 0; mt < 4; mt++) {
        const int r0 = brow + wm * 64 + mt * 16 + gr;
        #pragma unroll
        for (int nt = 0; nt < 8; nt++) {
            const int c = bcol + wn * 64 + nt * 8 + 2 * tig;
            const float b0 = bias[c], b1 = bias[c + 1];
            const float v0 = acc[mt][nt][0] + b0, v1 = acc[mt][nt][1] + b1;
            const float v2 = acc[mt][nt][2] + b0, v3 = acc[mt][nt][3] + b1;
            if (Cf) {
                float2 p0; p0.x = v0; p0.y = v1;
                float2 p1; p1.x = v2; p1.y = v3;
                *(float2*)&Cf[(size_t)r0 * N + c] = p0;
                *(float2*)&Cf[(size_t)(r0 + 8) * N + c] = p1;
            } else {
                *(uint32_t*)&Ch[(size_t)r0 * N + c] = packh2(v0, v1);
                *(uint32_t*)&Ch[(size_t)(r0 + 8) * N + c] = packh2(v2, v3);
            }
        }
    }
}

// ============================================================================
// Flash attention v2 style: Br=128 (8 warps x 16 rows), Bc=64.
// Warp owns full rows -> softmax in registers, P stays in registers,
// ONE __syncthreads per iteration, 3-stage cp.async K/V ring.
// Q projection carries qscale*log2(e); softmax uses exp2f.
// ============================================================================
#define KVBUF 34816                       // K[64][136] + V[64][136] bytes
#define ATT_SMEM (34816 + 3 * KVBUF)      // Q + 3-ring = 139264 B

__global__ __launch_bounds__(256, 1) void attn_h(
    const __half* __restrict__ QKV, __half* __restrict__ O)
{
    extern __shared__ char smc[];
    __half* Qs = (__half*)smc;                       // [128][136]

    const int tid = threadIdx.x, lane = tid & 31, wid = tid >> 5;
    const int gr = lane >> 2, tig = lane & 3;
    const int bh = blockIdx.y;
    const int b = bh >> 4, h = bh & 15, g = h >> 2;
    const int q0 = blockIdx.x * 128;

    const size_t rowbase = (size_t)b * SEQ * QKV_LD;

    // ---- issue Q load + KV tile 0 (group 0), KV tile 1 (group 1) ----
    {
        const int qr = tid >> 1, qc = (tid & 1) * 64;
        const __half* qp = QKV + rowbase + (size_t)(q0 + qr) * QKV_LD + h * HEAD_DIM + qc;
        __half* qs = &Qs[qr * 136 + qc];
        #pragma unroll
        for (int i = 0; i < 8; i++) cp16(qs + 8 * i, qp + 8 * i);
    }
    const int kvr = tid >> 2, kvc = (tid & 3) * 32;
    const __half* kbase = QKV + rowbase + (size_t)kvr * QKV_LD + 2048 + g * HEAD_DIM + kvc;
    {
        __half* ks = (__half*)(smc + 34816) + kvr * 136 + kvc;
        __half* vs = (__half*)(smc + 34816 + 17408) + kvr * 136 + kvc;
        #pragma unroll
        for (int i = 0; i < 4; i++) cp16(ks + 8 * i, kbase + 8 * i);
        #pragma unroll
        for (int i = 0; i < 4; i++) cp16(vs + 8 * i, kbase + 512 + 8 * i);
        cp_commit();
    }
    {
        const __half* kp = kbase + (size_t)64 * QKV_LD;
        __half* ks = (__half*)(smc + 34816 + KVBUF) + kvr * 136 + kvc;
        __half* vs = (__half*)(smc + 34816 + KVBUF + 17408) + kvr * 136 + kvc;
        #pragma unroll
        for (int i = 0; i < 4; i++) cp16(ks + 8 * i, kp + 8 * i);
        #pragma unroll
        for (int i = 0; i < 4; i++) cp16(vs + 8 * i, kp + 512 + 8 * i);
        cp_commit();
    }
    cp_wait<1>();
    __syncthreads();

    // ---- Q fragments to registers (warp owns rows 16*wid .. +15) ----
    uint32_t aq[8][4];
    {
        const int qa_off = (wid * 16 + (lane & 7) + ((lane >> 3) & 1) * 8) * 136 + (lane >> 4) * 8;
        const uint32_t qaddr = sm_u32(Qs) + 2u * qa_off;
        #pragma unroll
        for (int ks = 0; ks < 8; ks++) ldm_x4(aq[ks], qaddr + ks * 32);
    }

    // ldmatrix lane offsets for K (B, non-trans) and V (B, trans), in halfs
    const int kb_off = ((lane & 7) + (lane >> 4) * 8) * 136 + ((lane >> 3) & 1) * 8;
    const int vb_off = ((lane & 7) + ((lane >> 3) & 1) * 8) * 136 + (lane >> 4) * 8;

    float oacc[16][4] = {};
    float m0 = -1e30f, m1 = -1e30f, l0 = 0.f, l1 = 0.f;

    for (int it = 0; it < SEQ / 64; it++) {
        if (it > 0) {
            if (it < SEQ / 64 - 1) cp_wait<1>(); else cp_wait<0>();
            __syncthreads();   // tile `it` arrived AND everyone done reading buf (it-1)%3
        }
        // prefetch tile it+2 into buf (it+2)%3  (== buf (it-1)%3, safe after the sync)
        if (it + 2 < SEQ / 64) {
            const __half* kp = kbase + (size_t)(it + 2) * 64 * QKV_LD;
            char* bufc = smc + 34816 + ((it + 2) % 3) * KVBUF;
            __half* ks = (__half*)bufc + kvr * 136 + kvc;
            __half* vs = (__half*)(bufc + 17408) + kvr * 136 + kvc;
            #pragma unroll
            for (int i = 0; i < 4; i++) cp16(ks + 8 * i, kp + 8 * i);
            #pragma unroll
            for (int i = 0; i < 4; i++) cp16(vs + 8 * i, kp + 512 + 8 * i);
            cp_commit();
        }

        const char* bufc = smc + 34816 + (it % 3) * KVBUF;
        const uint32_t kaddr = sm_u32(bufc) + 2u * kb_off;
        const uint32_t vaddr = sm_u32(bufc + 17408) + 2u * vb_off;

        // ---- S = Q @ K^T : 16 rows x 64 cols per warp ----
        float sacc[8][4] = {};
        #pragma unroll
        for (int ks = 0; ks < 8; ks++) {
            #pragma unroll
            for (int ng = 0; ng < 4; ng++) {
                uint32_t bf[4];
                ldm_x4(bf, kaddr + ng * 16 * 272 + ks * 32);
                mma16(sacc[2 * ng], aq[ks], bf);
                mma16(sacc[2 * ng + 1], aq[ks], bf + 2);
            }
        }

        // ---- softmax in registers (rows gr and gr+8 of this warp's strip) ----
        float mx0 = sacc[0][0], mx1 = sacc[0][2];
        #pragma unroll
        for (int nt = 0; nt < 8; nt++) {
            mx0 = fmaxf(mx0, fmaxf(sacc[nt][0], sacc[nt][1]));
            mx1 = fmaxf(mx1, fmaxf(sacc[nt][2], sacc[nt][3]));
        }
        mx0 = fmaxf(mx0, __shfl_xor_sync(0xffffffffu, mx0, 1));
        mx0 = fmaxf(mx0, __shfl_xor_sync(0xffffffffu, mx0, 2));
        mx1 = fmaxf(mx1, __shfl_xor_sync(0xffffffffu, mx1, 1));
        mx1 = fmaxf(mx1, __shfl_xor_sync(0xffffffffu, mx1, 2));

        const float m0n = fmaxf(m0, mx0), m1n = fmaxf(m1, mx1);
        const float c0 = exp2f(m0 - m0n), c1 = exp2f(m1 - m1n);
        float s0 = 0.f, s1 = 0.f;
        #pragma unroll
        for (int nt = 0; nt < 8; nt++) {
            sacc[nt][0] = exp2f(sacc[nt][0] - m0n);
            sacc[nt][1] = exp2f(sacc[nt][1] - m0n);
            sacc[nt][2] = exp2f(sacc[nt][2] - m1n);
            sacc[nt][3] = exp2f(sacc[nt][3] - m1n);
            s0 += sacc[nt][0] + sacc[nt][1];
            s1 += sacc[nt][2] + sacc[nt][3];
        }
        s0 += __shfl_xor_sync(0xffffffffu, s0, 1);
        s0 += __shfl_xor_sync(0xffffffffu, s0, 2);
        s1 += __shfl_xor_sync(0xffffffffu, s1, 1);
        s1 += __shfl_xor_sync(0xffffffffu, s1, 2);
        l0 = l0 * c0 + s0; l1 = l1 * c1 + s1;
        m0 = m0n; m1 = m1n;

        #pragma unroll
        for (int nt = 0; nt < 16; nt++) {
            oacc[nt][0] *= c0; oacc[nt][1] *= c0;
            oacc[nt][2] *= c1; oacc[nt][3] *= c1;
        }

        // ---- pack P fragments in registers (C-layout -> A-layout) ----
        uint32_t pa[4][4];
        #pragma unroll
        for (int kk = 0; kk < 4; kk++) {
            pa[kk][0] = packh2(sacc[2 * kk][0],     sacc[2 * kk][1]);
            pa[kk][1] = packh2(sacc[2 * kk][2],     sacc[2 * kk][3]);
            pa[kk][2] = packh2(sacc[2 * kk + 1][0], sacc[2 * kk + 1][1]);
            pa[kk][3] = packh2(sacc[2 * kk + 1][2], sacc[2 * kk + 1][3]);
        }

        // ---- O += P @ V : 16 rows x 128 cols per warp ----
        #pragma unroll
        for (int kk = 0; kk < 4; kk++) {
            #pragma unroll
            for (int ng = 0; ng < 8; ng++) {
                uint32_t vf[4];
                ldm_x4t(vf, vaddr + kk * 16 * 272 + ng * 32);
                mma16(oacc[2 * ng], pa[kk], vf);
                mma16(oacc[2 * ng + 1], pa[kk], vf + 2);
            }
        }
    }

    // ---- finalize ----
    const float il0 = 1.f / l0, il1 = 1.f / l1;
    const int r0 = q0 + wid * 16 + gr;
    __half* o0 = O + (size_t)(b * SEQ + r0) * D_MODEL + h * HEAD_DIM;
    __half* o1 = O + (size_t)(b * SEQ + r0 + 8) * D_MODEL + h * HEAD_DIM;
    #pragma unroll
    for (int nt = 0; nt < 16; nt++) {
        const int c = nt * 8 + 2 * tig;
        *(uint32_t*)&o0[c] = packh2(oacc[nt][0] * il0, oacc[nt][1] * il0);
        *(uint32_t*)&o1[c] = packh2(oacc[nt][2] * il1, oacc[nt][3] * il1);
    }
}

// ============================================================================
extern "C" void kernel_launch(void* const* d_in, const int* in_sizes, int n_in,
                              void* d_out, int out_size)
{
    const float* x  = (const float*)d_in[0];
    const float* Wq = (const float*)d_in[1];
    const float* bq = (const float*)d_in[2];
    const float* Wk = (const float*)d_in[3];
    const float* bk = (const float*)d_in[4];
    const float* Wv = (const float*)d_in[5];
    const float* bv = (const float*)d_in[6];
    const float* Wo = (const float*)d_in[7];
    const float* bo = (const float*)d_in[8];
    float* out = (float*)d_out;

    __half *xh, *wqkvt, *wot, *qkvh, *attnh;
    float *bqkv;
    cudaGetSymbolAddress((void**)&xh, g_xh);
    cudaGetSymbolAddress((void**)&wqkvt, g_wqkvt);
    cudaGetSymbolAddress((void**)&bqkv, g_bqkv);
    cudaGetSymbolAddress((void**)&wot, g_wot);
    cudaGetSymbolAddress((void**)&qkvh, g_qkvh);
    cudaGetSymbolAddress((void**)&attnh, g_attnh);

    cudaFuncSetAttribute(gemm_h, cudaFuncAttributeMaxDynamicSharedMemorySize, GEMM_SMEM);
    cudaFuncSetAttribute(attn_h, cudaFuncAttributeMaxDynamicSharedMemorySize, ATT_SMEM);

    // 1/sqrt(128) * log2(e): softmax computed in exp2 domain
    const float qscale = 0.08838834764831845f * 1.4426950408889634f;
    const int NX = ROWS * D_MODEL;

    f2h_kernel<<<(NX + 255) / 256, 256>>>(x, xh, NX);
    transpose_f2h<<<dim3(D_MODEL / 32, D_MODEL / 32), dim3(32, 8)>>>(
        Wq, wqkvt, D_MODEL, D_MODEL, qscale);
    transpose_f2h<<<dim3(KV_COLS / 32, D_MODEL / 32), dim3(32, 8)>>>(
        Wk, wqkvt + 2048 * D_MODEL, D_MODEL, KV_COLS, 1.0f);
    transpose_f2h<<<dim3(KV_COLS / 32, D_MODEL / 32), dim3(32, 8)>>>(
        Wv, wqkvt + 2560 * D_MODEL, D_MODEL, KV_COLS, 1.0f);
    transpose_f2h<<<dim3(D_MODEL / 32, D_MODEL / 32), dim3(32, 8)>>>(
        Wo, wot, D_MODEL, D_MODEL, 1.0f);
    concat_bias<<<QKV_LD / 256, 256>>>(bq, bk, bv, bqkv, qscale);

    gemm_h<<<dim3(QKV_LD / 256, ROWS / 128), 256, GEMM_SMEM>>>(
        xh, wqkvt, bqkv, nullptr, qkvh, ROWS, QKV_LD, D_MODEL);

    attn_h<<<dim3(SEQ / 128, BATCH * NUM_HEADS), 256, ATT_SMEM>>>(qkvh, attnh);

    gemm_h<<<dim3(D_MODEL / 256, ROWS / 128), 256, GEMM_SMEM>>>(
        attnh, wot, bo, out, nullptr, ROWS, D_MODEL, D_MODEL);
}